// round 11
// baseline (speedup 1.0000x reference)
#include <cuda_runtime.h>
#include <cuda_fp16.h>
#include <cstdint>

// MaddnessConv2d, round 11: global fp16 LUT (pre-converted once, L1-resident)
// + 4 lanes/pixel, 784 blocks x 256 threads -> ~40 warps/SM, no per-block
// LUT setup, fp16-packed stride-65 transpose, two-tree fp16 accumulation.
//
//   x:            (16, 64, 56, 56) f32
//   split_idxs:   (16, 4) i32
//   split_vals:   (16, 4, 8) f32
//   lookup_tables:(16, 16, 64) f32
//   bias:         (64,) f32
//   out:          (16, 64, 56, 56) f32
//
// out[p][ch] = sum_cb LUT[cb][e_cb(p)][ch] + bias[ch]. LUT rows (cb,e) are
// 128B fp16 in a __device__ global (32KB, hot in L1). Lane `part` of a pixel
// owns channels [16part, 16part+16) = bytes [32part, 32part+32) of each row
// (2 x LDG.128, sector-aligned). Codes: 4 cbs/lane + 2 butterfly shuffles.

#define NCB   16
#define HW    3136          // 56*56
#define WID   56
#define TPB   256
#define NBLK  784           // 784*256 == 4*50176 exactly; 64 pixels/block

// fp16 LUT: row r = cb*16+e is 8 uint4 (64 half); element (r,ch8) at r*8+ch8.
__device__ uint4 g_lut16[2048];

__global__ void convert_lut_kernel(const float* __restrict__ lut) {
    const int i = blockIdx.x * blockDim.x + threadIdx.x;   // 0..2047
    const float4* l4 = (const float4*)lut;
    float4 a = l4[i * 2];
    float4 b = l4[i * 2 + 1];
    __half2 h0 = __floats2half2_rn(a.x, a.y);
    __half2 h1 = __floats2half2_rn(a.z, a.w);
    __half2 h2 = __floats2half2_rn(b.x, b.y);
    __half2 h3 = __floats2half2_rn(b.z, b.w);
    uint4 pk;
    pk.x = *(unsigned*)&h0;
    pk.y = *(unsigned*)&h1;
    pk.z = *(unsigned*)&h2;
    pk.w = *(unsigned*)&h3;
    g_lut16[i] = pk;
}

__global__ __launch_bounds__(TPB, 4) void maddness_conv2d_kernel(
    const float* __restrict__ x,
    const int*   __restrict__ split_idxs,
    const float* __restrict__ split_vals,
    const float* __restrict__ bias,
    float*       __restrict__ out)
{
    __shared__ float4 s_buf[8 * 65];       // transpose buf: [g:8][px:64] pad 65
    __shared__ float  s_bias[64];
    __shared__ float  s_sval[16 * 33];     // stride-33: conflict-light walk
    __shared__ int    s_off[64];
    __shared__ int    s_kpos[64];

    const int tid = threadIdx.x;

    // --- tiny table fill (no big LUT setup anymore) ---
    if (tid < 64) {
        int cb = tid >> 2;                 // tid = cb*4 + t
        int si = split_idxs[tid];
        int f  = cb * 36 + si;
        int ch = f / 9;
        int r  = f - ch * 9;               // kernel position 0..8
        int dy = r / 3 - 1;
        int dx = r - (r / 3) * 3 - 1;
        s_off[tid]  = ch * HW + dy * WID + dx;
        s_kpos[tid] = r;
        s_bias[tid] = bias[tid];
    }
    #pragma unroll
    for (int i = tid; i < NCB * 32; i += TPB)
        s_sval[(i >> 5) * 33 + (i & 31)] = split_vals[i];
    __syncthreads();

    // --- indices: 4 lanes per pixel ---
    const int gt   = blockIdx.x * TPB + tid;   // exact grid
    const int p    = gt >> 2;                  // pixel
    const int part = gt & 3;                   // channel/codebook quarter
    const int b    = p / HW;
    const int rem  = p - b * HW;
    const int y    = rem / WID;
    const int xw   = rem - y * WID;
    const float* xb = x + (size_t)b * 64 * HW + rem;

    // 3x3 validity bitmask (pad=1)
    unsigned vm = 0;
    #pragma unroll
    for (int ki = 0; ki < 3; ki++)
        #pragma unroll
        for (int kj = 0; kj < 3; kj++) {
            bool ok = ((unsigned)(y + ki - 1) < 56u) & ((unsigned)(xw + kj - 1) < 56u);
            vm |= (ok ? 1u : 0u) << (ki * 3 + kj);
        }

    // --- upfront gathers for my 4 codebooks (MLP=16) ---
    float v[16];
    #pragma unroll
    for (int c = 0; c < 4; c++)
        #pragma unroll
        for (int t = 0; t < 4; t++) {
            const int idx = (4 * part + c) * 4 + t;
            v[c * 4 + t] =
                ((vm >> s_kpos[idx]) & 1u) ? __ldg(xb + s_off[idx]) : 0.0f;
        }

    // --- threshold walk ---
    unsigned mine = 0;
    #pragma unroll
    for (int c = 0; c < 4; c++) {
        const int cb = 4 * part + c;
        int e = 0;
        #pragma unroll
        for (int t = 0; t < 4; t++) {
            const float thr = s_sval[cb * 33 + t * 8 + e];
            e = 2 * e + (v[c * 4 + t] >= thr ? 1 : 0);
        }
        mine |= (unsigned)e << (4 * c);
    }

    // Merge codes across the 4 lanes of this pixel (lane bits 0-1 = part).
    unsigned long long codes = (unsigned long long)mine << (16 * part);
    codes |= __shfl_xor_sync(0xffffffffu, codes, 1);
    codes |= __shfl_xor_sync(0xffffffffu, codes, 2);

    // --- accumulate ch [16part, 16part+16) over 16 cbs, two fp16 trees ---
    const uint4* lutp = g_lut16 + part * 2;
    __half2 accA[2][4], accB[2][4];
    #pragma unroll
    for (int j = 0; j < 2; j++)
        #pragma unroll
        for (int k = 0; k < 4; k++) {
            accA[j][k] = __half2half2(__ushort_as_half(0));
            accB[j][k] = __half2half2(__ushort_as_half(0));
        }

    #pragma unroll
    for (int cb = 0; cb < 8; cb++) {
        const int eA = (int)((codes >> (4 * cb)) & 15ull);
        const int eB = (int)((codes >> (4 * (cb + 8))) & 15ull);
        const uint4* rA = lutp + ((cb * 16 + eA) << 3);
        const uint4* rB = lutp + (((cb + 8) * 16 + eB) << 3);
        uint4 a0 = __ldg(rA);
        uint4 a1 = __ldg(rA + 1);
        uint4 b0 = __ldg(rB);
        uint4 b1 = __ldg(rB + 1);
        accA[0][0] = __hadd2(accA[0][0], *(__half2*)&a0.x);
        accA[0][1] = __hadd2(accA[0][1], *(__half2*)&a0.y);
        accA[0][2] = __hadd2(accA[0][2], *(__half2*)&a0.z);
        accA[0][3] = __hadd2(accA[0][3], *(__half2*)&a0.w);
        accA[1][0] = __hadd2(accA[1][0], *(__half2*)&a1.x);
        accA[1][1] = __hadd2(accA[1][1], *(__half2*)&a1.y);
        accA[1][2] = __hadd2(accA[1][2], *(__half2*)&a1.z);
        accA[1][3] = __hadd2(accA[1][3], *(__half2*)&a1.w);
        accB[0][0] = __hadd2(accB[0][0], *(__half2*)&b0.x);
        accB[0][1] = __hadd2(accB[0][1], *(__half2*)&b0.y);
        accB[0][2] = __hadd2(accB[0][2], *(__half2*)&b0.z);
        accB[0][3] = __hadd2(accB[0][3], *(__half2*)&b0.w);
        accB[1][0] = __hadd2(accB[1][0], *(__half2*)&b1.x);
        accB[1][1] = __hadd2(accB[1][1], *(__half2*)&b1.y);
        accB[1][2] = __hadd2(accB[1][2], *(__half2*)&b1.z);
        accB[1][3] = __hadd2(accB[1][3], *(__half2*)&b1.w);
    }

    // --- fp16 tree merge + transpose (stride-65: bank-conflict-free) ---
    const int pxl = tid >> 2;                  // local pixel 0..63
    #pragma unroll
    for (int j = 0; j < 2; j++) {
        __half2 m0 = __hadd2(accA[j][0], accB[j][0]);
        __half2 m1 = __hadd2(accA[j][1], accB[j][1]);
        __half2 m2 = __hadd2(accA[j][2], accB[j][2]);
        __half2 m3 = __hadd2(accA[j][3], accB[j][3]);
        float4 pk;
        pk.x = *(float*)&m0;
        pk.y = *(float*)&m1;
        pk.z = *(float*)&m2;
        pk.w = *(float*)&m3;
        s_buf[(2 * part + j) * 65 + pxl] = pk; // group g = 2*part + j (8 ch)
    }
    __syncthreads();

    // --- coalesced stores with fp32 finalize + bias ---
    // thread (gq = tid>>6, px = tid&63) stores groups {2gq, 2gq+1}.
    const int gq = tid >> 6;
    const int px = tid & 63;
    const int pg = blockIdx.x * 64 + px;       // global pixel
    const int bb = pg / HW;
    const int rr2 = pg - bb * HW;
    float* ob = out + (size_t)bb * 64 * HW + rr2;

    #pragma unroll
    for (int jj = 0; jj < 2; jj++) {
        const int g = 2 * gq + jj;
        float4 pk = s_buf[g * 65 + px];
        float2 f0 = __half22float2(*(__half2*)&pk.x);
        float2 f1 = __half22float2(*(__half2*)&pk.y);
        float2 f2 = __half22float2(*(__half2*)&pk.z);
        float2 f3 = __half22float2(*(__half2*)&pk.w);
        const int ch = 8 * g;
        ob[(ch + 0) * HW] = f0.x + s_bias[ch + 0];
        ob[(ch + 1) * HW] = f0.y + s_bias[ch + 1];
        ob[(ch + 2) * HW] = f1.x + s_bias[ch + 2];
        ob[(ch + 3) * HW] = f1.y + s_bias[ch + 3];
        ob[(ch + 4) * HW] = f2.x + s_bias[ch + 4];
        ob[(ch + 5) * HW] = f2.y + s_bias[ch + 5];
        ob[(ch + 6) * HW] = f3.x + s_bias[ch + 6];
        ob[(ch + 7) * HW] = f3.y + s_bias[ch + 7];
    }
}

extern "C" void kernel_launch(void* const* d_in, const int* in_sizes, int n_in,
                              void* d_out, int out_size)
{
    const float* x    = (const float*)d_in[0];
    const int*   sidx = (const int*)  d_in[1];
    const float* sval = (const float*)d_in[2];
    const float* lut  = (const float*)d_in[3];
    const float* bias = (const float*)d_in[4];
    float* out = (float*)d_out;

    convert_lut_kernel<<<8, 256>>>(lut);
    maddness_conv2d_kernel<<<NBLK, TPB>>>(x, sidx, sval, bias, out);
}

// round 12
// speedup vs baseline: 1.1385x; 1.1385x over previous
#include <cuda_runtime.h>
#include <cuda_fp16.h>
#include <cstdint>

// MaddnessConv2d, round 12: one-time global fp16 LUT conversion + per-block
// 32KB smem memcpy (no per-block math), 4 lanes/pixel, grid 784, 32 warps/SM.
//
//   x:            (16, 64, 56, 56) f32
//   split_idxs:   (16, 4) i32
//   split_vals:   (16, 4, 8) f32
//   lookup_tables:(16, 16, 64) f32
//   bias:         (64,) f32
//   out:          (16, 64, 56, 56) f32
//
// out[p][ch] = sum_cb LUT[cb][e_cb(p)][ch] + bias[ch]. LUT rows (cb,e) are
// 128B fp16 (8 uint4 slots of 8 channels). Lane `part` in {0..3} of a pixel
// owns slots {2part, 2part+1}, visited in parity order k = (j + p) & 1 so
// each 8-lane LDS phase (2 px x 4 parts) covers all 8 banks regardless of
// the data-dependent code e. Two fp16 trees (cb 0-7 / 8-15), merged in fp16,
// fp32 finalize + bias at the coalesced store.

#define NCB   16
#define HW    3136          // 56*56
#define WID   56
#define TPB   256
#define NBLK  784           // 784*256 == 4*50176 exactly; 64 pixels/block

__device__ uint4 g_lut16[2048];   // row r = cb*16+e at [r*8 .. r*8+8)

__global__ void convert_lut_kernel(const float* __restrict__ lut) {
    const int i = blockIdx.x * blockDim.x + threadIdx.x;   // 0..2047
    const float4* l4 = (const float4*)lut;
    float4 a = l4[i * 2];
    float4 b = l4[i * 2 + 1];
    __half2 h0 = __floats2half2_rn(a.x, a.y);
    __half2 h1 = __floats2half2_rn(a.z, a.w);
    __half2 h2 = __floats2half2_rn(b.x, b.y);
    __half2 h3 = __floats2half2_rn(b.z, b.w);
    uint4 pk;
    pk.x = *(unsigned*)&h0;
    pk.y = *(unsigned*)&h1;
    pk.z = *(unsigned*)&h2;
    pk.w = *(unsigned*)&h3;
    g_lut16[i] = pk;
}

__global__ __launch_bounds__(TPB, 4) void maddness_conv2d_kernel(
    const float* __restrict__ x,
    const int*   __restrict__ split_idxs,
    const float* __restrict__ split_vals,
    const float* __restrict__ bias,
    float*       __restrict__ out)
{
    __shared__ uint4  s_lut[2048];        // 32KB; reused as transpose buffer
    __shared__ float  s_bias[64];
    __shared__ float  s_sval[16 * 33];    // stride-33 conflict-free walk
    __shared__ int    s_off[64];
    __shared__ int    s_kpos[64];

    const int tid = threadIdx.x;

    // --- per-block setup: pure 32KB copy (L2-broadcast), no math ---
    #pragma unroll
    for (int i = tid; i < 2048; i += TPB) s_lut[i] = g_lut16[i];
    if (tid < 64) {
        int cb = tid >> 2;                 // tid = cb*4 + t
        int si = split_idxs[tid];
        int f  = cb * 36 + si;
        int ch = f / 9;
        int r  = f - ch * 9;               // kernel position 0..8
        int dy = r / 3 - 1;
        int dx = r - (r / 3) * 3 - 1;
        s_off[tid]  = ch * HW + dy * WID + dx;
        s_kpos[tid] = r;
        s_bias[tid] = bias[tid];
    }
    #pragma unroll
    for (int i = tid; i < NCB * 32; i += TPB)
        s_sval[(i >> 5) * 33 + (i & 31)] = split_vals[i];
    __syncthreads();

    // --- indices: 4 lanes per pixel ---
    const int gt   = blockIdx.x * TPB + tid;   // exact grid
    const int p    = gt >> 2;                  // pixel
    const int part = gt & 3;                   // channel/codebook quarter
    const int b    = p / HW;
    const int rem  = p - b * HW;
    const int y    = rem / WID;
    const int xw   = rem - y * WID;
    const float* xb = x + (size_t)b * 64 * HW + rem;

    // 3x3 validity bitmask (pad=1)
    unsigned vm = 0;
    #pragma unroll
    for (int ki = 0; ki < 3; ki++)
        #pragma unroll
        for (int kj = 0; kj < 3; kj++) {
            bool ok = ((unsigned)(y + ki - 1) < 56u) & ((unsigned)(xw + kj - 1) < 56u);
            vm |= (ok ? 1u : 0u) << (ki * 3 + kj);
        }

    // --- upfront gathers for my 4 codebooks (MLP=16) ---
    float v[16];
    #pragma unroll
    for (int c = 0; c < 4; c++)
        #pragma unroll
        for (int t = 0; t < 4; t++) {
            const int idx = (4 * part + c) * 4 + t;
            v[c * 4 + t] =
                ((vm >> s_kpos[idx]) & 1u) ? __ldg(xb + s_off[idx]) : 0.0f;
        }

    // --- threshold walk ---
    unsigned mine = 0;
    #pragma unroll
    for (int c = 0; c < 4; c++) {
        const int cb = 4 * part + c;
        int e = 0;
        #pragma unroll
        for (int t = 0; t < 4; t++) {
            const float thr = s_sval[cb * 33 + t * 8 + e];
            e = 2 * e + (v[c * 4 + t] >= thr ? 1 : 0);
        }
        mine |= (unsigned)e << (4 * c);
    }

    // Merge codes across the 4 lanes of this pixel (lane bits 0-1 = part).
    unsigned long long codes = (unsigned long long)mine << (16 * part);
    codes |= __shfl_xor_sync(0xffffffffu, codes, 1);
    codes |= __shfl_xor_sync(0xffffffffu, codes, 2);

    // --- accumulate ch [16part, 16part+16), two fp16 trees ---
    // slot order: sl_j = 2part + ((j + p) & 1): 8-lane phase covers 8 banks.
    const int px1 = p & 1;
    const int sl0 = 2 * part + px1;
    const int sl1 = 2 * part + (px1 ^ 1);

    __half2 acc0A[4], acc0B[4], acc1A[4], acc1B[4];
    #pragma unroll
    for (int k = 0; k < 4; k++) {
        acc0A[k] = __half2half2(__ushort_as_half(0));
        acc0B[k] = __half2half2(__ushort_as_half(0));
        acc1A[k] = __half2half2(__ushort_as_half(0));
        acc1B[k] = __half2half2(__ushort_as_half(0));
    }

    #pragma unroll
    for (int cb = 0; cb < 8; cb++) {
        const int eA = (int)((codes >> (4 * cb)) & 15ull);
        const int eB = (int)((codes >> (4 * (cb + 8))) & 15ull);
        const uint4* rowA = s_lut + (cb * 16 + eA) * 8;
        const uint4* rowB = s_lut + ((cb + 8) * 16 + eB) * 8;
        uint4 a0 = rowA[sl0];
        uint4 b0 = rowB[sl0];
        uint4 a1 = rowA[sl1];
        uint4 b1 = rowB[sl1];
        acc0A[0] = __hadd2(acc0A[0], *(__half2*)&a0.x);
        acc0A[1] = __hadd2(acc0A[1], *(__half2*)&a0.y);
        acc0A[2] = __hadd2(acc0A[2], *(__half2*)&a0.z);
        acc0A[3] = __hadd2(acc0A[3], *(__half2*)&a0.w);
        acc0B[0] = __hadd2(acc0B[0], *(__half2*)&b0.x);
        acc0B[1] = __hadd2(acc0B[1], *(__half2*)&b0.y);
        acc0B[2] = __hadd2(acc0B[2], *(__half2*)&b0.z);
        acc0B[3] = __hadd2(acc0B[3], *(__half2*)&b0.w);
        acc1A[0] = __hadd2(acc1A[0], *(__half2*)&a1.x);
        acc1A[1] = __hadd2(acc1A[1], *(__half2*)&a1.y);
        acc1A[2] = __hadd2(acc1A[2], *(__half2*)&a1.z);
        acc1A[3] = __hadd2(acc1A[3], *(__half2*)&a1.w);
        acc1B[0] = __hadd2(acc1B[0], *(__half2*)&b1.x);
        acc1B[1] = __hadd2(acc1B[1], *(__half2*)&b1.y);
        acc1B[2] = __hadd2(acc1B[2], *(__half2*)&b1.z);
        acc1B[3] = __hadd2(acc1B[3], *(__half2*)&b1.w);
    }

    // --- fp16 merge + transpose into dead LUT region (pad-10, conflict-free) ---
    __syncthreads();                           // s_lut reads done block-wide
    uint4* s_buf = s_lut;                      // [px:64][g:8] at px*10 + g
    const int pxl = tid >> 2;                  // local pixel 0..63
    {
        __half2 m0 = __hadd2(acc0A[0], acc0B[0]);
        __half2 m1 = __hadd2(acc0A[1], acc0B[1]);
        __half2 m2 = __hadd2(acc0A[2], acc0B[2]);
        __half2 m3 = __hadd2(acc0A[3], acc0B[3]);
        uint4 pk;
        pk.x = *(unsigned*)&m0;
        pk.y = *(unsigned*)&m1;
        pk.z = *(unsigned*)&m2;
        pk.w = *(unsigned*)&m3;
        s_buf[pxl * 10 + sl0] = pk;            // group g == slot index
        m0 = __hadd2(acc1A[0], acc1B[0]);
        m1 = __hadd2(acc1A[1], acc1B[1]);
        m2 = __hadd2(acc1A[2], acc1B[2]);
        m3 = __hadd2(acc1A[3], acc1B[3]);
        pk.x = *(unsigned*)&m0;
        pk.y = *(unsigned*)&m1;
        pk.z = *(unsigned*)&m2;
        pk.w = *(unsigned*)&m3;
        s_buf[pxl * 10 + sl1] = pk;
    }
    __syncthreads();

    // --- coalesced stores with fp32 finalize + bias ---
    // thread (gq = tid>>6, px = tid&63) stores groups {2gq, 2gq+1}.
    const int gq = tid >> 6;
    const int px = tid & 63;
    const int pg = blockIdx.x * 64 + px;       // global pixel
    const int bb = pg / HW;
    const int rr2 = pg - bb * HW;
    float* ob = out + (size_t)bb * 64 * HW + rr2;

    #pragma unroll
    for (int jj = 0; jj < 2; jj++) {
        const int g = 2 * gq + jj;
        uint4 pk = s_buf[px * 10 + g];
        float2 f0 = __half22float2(*(__half2*)&pk.x);
        float2 f1 = __half22float2(*(__half2*)&pk.y);
        float2 f2 = __half22float2(*(__half2*)&pk.z);
        float2 f3 = __half22float2(*(__half2*)&pk.w);
        const int ch = 8 * g;
        ob[(ch + 0) * HW] = f0.x + s_bias[ch + 0];
        ob[(ch + 1) * HW] = f0.y + s_bias[ch + 1];
        ob[(ch + 2) * HW] = f1.x + s_bias[ch + 2];
        ob[(ch + 3) * HW] = f1.y + s_bias[ch + 3];
        ob[(ch + 4) * HW] = f2.x + s_bias[ch + 4];
        ob[(ch + 5) * HW] = f2.y + s_bias[ch + 5];
        ob[(ch + 6) * HW] = f3.x + s_bias[ch + 6];
        ob[(ch + 7) * HW] = f3.y + s_bias[ch + 7];
    }
}

extern "C" void kernel_launch(void* const* d_in, const int* in_sizes, int n_in,
                              void* d_out, int out_size)
{
    const float* x    = (const float*)d_in[0];
    const int*   sidx = (const int*)  d_in[1];
    const float* sval = (const float*)d_in[2];
    const float* lut  = (const float*)d_in[3];
    const float* bias = (const float*)d_in[4];
    float* out = (float*)d_out;

    convert_lut_kernel<<<8, 256>>>(lut);
    maddness_conv2d_kernel<<<NBLK, TPB>>>(x, sidx, sval, bias, out);
}

// round 13
// speedup vs baseline: 1.2959x; 1.1382x over previous
#include <cuda_runtime.h>
#include <cuda_fp16.h>
#include <cstdint>

// MaddnessConv2d, round 13: persistent single-wave kernel.
// Grid = 592 = 4 CTAs/SM x 148 (one full wave, 32 warps/SM). Each block
// converts the LUT fp32->fp16 into smem ONCE, then grid-strides over 64-px
// tiles (784 tiles). Inner loop = R12's conflict-free 4-lanes/pixel scheme.
//
//   x:            (16, 64, 56, 56) f32
//   split_idxs:   (16, 4) i32
//   split_vals:   (16, 4, 8) f32
//   lookup_tables:(16, 16, 64) f32
//   bias:         (64,) f32
//   out:          (16, 64, 56, 56) f32
//
// out[p][ch] = sum_cb LUT[cb][e_cb(p)][ch] + bias[ch]. LUT rows (cb,e) are
// 128B fp16 (8 uint4 slots of 8 channels). Lane `part` in {0..3} of a pixel
// owns slots {2part, 2part+1}, visited in parity order (j + p) & 1 so each
// 8-lane LDS phase (2 px x 4 parts) covers all 8 banks regardless of the
// data-dependent code e. Two fp16 trees (cb 0-7 / 8-15) merged in fp16,
// fp32 finalize + bias at the coalesced store.

#define NCB    16
#define HW     3136         // 56*56
#define WID    56
#define TPB    256
#define NBLK   592          // 4 CTAs/SM x 148 SMs: exactly one wave
#define NTILES 784          // 784 x 64 px == 50176

__global__ __launch_bounds__(TPB, 4) void maddness_conv2d_kernel(
    const float* __restrict__ x,
    const int*   __restrict__ split_idxs,
    const float* __restrict__ split_vals,
    const float* __restrict__ lut,
    const float* __restrict__ bias,
    float*       __restrict__ out)
{
    __shared__ uint4  s_lut[2048];        // 32KB fp16 LUT, live whole kernel
    __shared__ uint4  s_buf[64 * 10];     // 10KB transpose buf [px:64][g:8] pad10
    __shared__ float  s_bias[64];
    __shared__ float  s_sval[16 * 33];    // stride-33 conflict-free walk
    __shared__ int    s_off[64];
    __shared__ int    s_kpos[64];

    const int tid = threadIdx.x;

    // --- one-time per-block setup: convert LUT fp32 -> fp16 into smem ---
    {
        const float4* lut4 = (const float4*)lut;   // 4096 float4 (4 ch each)
        char* s_lutb = (char*)s_lut;
        #pragma unroll
        for (int i = tid; i < 4096; i += TPB) {
            float4 lv = lut4[i];
            __half2 h0 = __floats2half2_rn(lv.x, lv.y);
            __half2 h1 = __floats2half2_rn(lv.z, lv.w);
            uint2 pk;
            pk.x = *(unsigned*)&h0;
            pk.y = *(unsigned*)&h1;
            // i = row*16 + ch4: row r at bytes [r*128, r*128+128)
            *(uint2*)(s_lutb + (i >> 4) * 128 + (i & 15) * 8) = pk;
        }
    }
    if (tid < 64) {
        int cb = tid >> 2;                 // tid = cb*4 + t
        int si = split_idxs[tid];
        int f  = cb * 36 + si;
        int ch = f / 9;
        int r  = f - ch * 9;               // kernel position 0..8
        int dy = r / 3 - 1;
        int dx = r - (r / 3) * 3 - 1;
        s_off[tid]  = ch * HW + dy * WID + dx;
        s_kpos[tid] = r;
        s_bias[tid] = bias[tid];
    }
    #pragma unroll
    for (int i = tid; i < NCB * 32; i += TPB)
        s_sval[(i >> 5) * 33 + (i & 31)] = split_vals[i];
    __syncthreads();

    const int part = tid & 3;              // channel/codebook quarter
    const int pxl  = tid >> 2;             // local pixel 0..63

    // --- persistent tile loop ---
    for (int tile = blockIdx.x; tile < NTILES; tile += NBLK) {
        const int p   = tile * 64 + pxl;   // global pixel
        const int b   = p / HW;
        const int rem = p - b * HW;
        const int y   = rem / WID;
        const int xw  = rem - y * WID;
        const float* xb = x + (size_t)b * 64 * HW + rem;

        // 3x3 validity bitmask (pad=1)
        unsigned vm = 0;
        #pragma unroll
        for (int ki = 0; ki < 3; ki++)
            #pragma unroll
            for (int kj = 0; kj < 3; kj++) {
                bool ok = ((unsigned)(y + ki - 1) < 56u) &
                          ((unsigned)(xw + kj - 1) < 56u);
                vm |= (ok ? 1u : 0u) << (ki * 3 + kj);
            }

        // upfront gathers for my 4 codebooks (MLP=16)
        float v[16];
        #pragma unroll
        for (int c = 0; c < 4; c++)
            #pragma unroll
            for (int t = 0; t < 4; t++) {
                const int idx = (4 * part + c) * 4 + t;
                v[c * 4 + t] =
                    ((vm >> s_kpos[idx]) & 1u) ? __ldg(xb + s_off[idx]) : 0.0f;
            }

        // threshold walk
        unsigned mine = 0;
        #pragma unroll
        for (int c = 0; c < 4; c++) {
            const int cb = 4 * part + c;
            int e = 0;
            #pragma unroll
            for (int t = 0; t < 4; t++) {
                const float thr = s_sval[cb * 33 + t * 8 + e];
                e = 2 * e + (v[c * 4 + t] >= thr ? 1 : 0);
            }
            mine |= (unsigned)e << (4 * c);
        }

        // merge codes across the 4 lanes of this pixel
        unsigned long long codes = (unsigned long long)mine << (16 * part);
        codes |= __shfl_xor_sync(0xffffffffu, codes, 1);
        codes |= __shfl_xor_sync(0xffffffffu, codes, 2);

        // accumulate ch [16part,16part+16), two fp16 trees; parity slot order
        const int px1 = p & 1;
        const int sl0 = 2 * part + px1;
        const int sl1 = 2 * part + (px1 ^ 1);

        __half2 acc0A[4], acc0B[4], acc1A[4], acc1B[4];
        #pragma unroll
        for (int k = 0; k < 4; k++) {
            acc0A[k] = __half2half2(__ushort_as_half(0));
            acc0B[k] = __half2half2(__ushort_as_half(0));
            acc1A[k] = __half2half2(__ushort_as_half(0));
            acc1B[k] = __half2half2(__ushort_as_half(0));
        }

        #pragma unroll
        for (int cb = 0; cb < 8; cb++) {
            const int eA = (int)((codes >> (4 * cb)) & 15ull);
            const int eB = (int)((codes >> (4 * (cb + 8))) & 15ull);
            const uint4* rowA = s_lut + (cb * 16 + eA) * 8;
            const uint4* rowB = s_lut + ((cb + 8) * 16 + eB) * 8;
            uint4 a0 = rowA[sl0];
            uint4 b0 = rowB[sl0];
            uint4 a1 = rowA[sl1];
            uint4 b1 = rowB[sl1];
            acc0A[0] = __hadd2(acc0A[0], *(__half2*)&a0.x);
            acc0A[1] = __hadd2(acc0A[1], *(__half2*)&a0.y);
            acc0A[2] = __hadd2(acc0A[2], *(__half2*)&a0.z);
            acc0A[3] = __hadd2(acc0A[3], *(__half2*)&a0.w);
            acc0B[0] = __hadd2(acc0B[0], *(__half2*)&b0.x);
            acc0B[1] = __hadd2(acc0B[1], *(__half2*)&b0.y);
            acc0B[2] = __hadd2(acc0B[2], *(__half2*)&b0.z);
            acc0B[3] = __hadd2(acc0B[3], *(__half2*)&b0.w);
            acc1A[0] = __hadd2(acc1A[0], *(__half2*)&a1.x);
            acc1A[1] = __hadd2(acc1A[1], *(__half2*)&a1.y);
            acc1A[2] = __hadd2(acc1A[2], *(__half2*)&a1.z);
            acc1A[3] = __hadd2(acc1A[3], *(__half2*)&a1.w);
            acc1B[0] = __hadd2(acc1B[0], *(__half2*)&b1.x);
            acc1B[1] = __hadd2(acc1B[1], *(__half2*)&b1.y);
            acc1B[2] = __hadd2(acc1B[2], *(__half2*)&b1.z);
            acc1B[3] = __hadd2(acc1B[3], *(__half2*)&b1.w);
        }

        // fp16 merge + transpose (pad-10: write phases conflict-free)
        __syncthreads();                   // prev tile's s_buf reads done
        {
            __half2 m0 = __hadd2(acc0A[0], acc0B[0]);
            __half2 m1 = __hadd2(acc0A[1], acc0B[1]);
            __half2 m2 = __hadd2(acc0A[2], acc0B[2]);
            __half2 m3 = __hadd2(acc0A[3], acc0B[3]);
            uint4 pk;
            pk.x = *(unsigned*)&m0;
            pk.y = *(unsigned*)&m1;
            pk.z = *(unsigned*)&m2;
            pk.w = *(unsigned*)&m3;
            s_buf[pxl * 10 + sl0] = pk;    // group g == slot index
            m0 = __hadd2(acc1A[0], acc1B[0]);
            m1 = __hadd2(acc1A[1], acc1B[1]);
            m2 = __hadd2(acc1A[2], acc1B[2]);
            m3 = __hadd2(acc1A[3], acc1B[3]);
            pk.x = *(unsigned*)&m0;
            pk.y = *(unsigned*)&m1;
            pk.z = *(unsigned*)&m2;
            pk.w = *(unsigned*)&m3;
            s_buf[pxl * 10 + sl1] = pk;
        }
        __syncthreads();

        // coalesced stores with fp32 finalize + bias
        const int gq = tid >> 6;           // 0..3
        const int px = tid & 63;
        const int pg = tile * 64 + px;     // global pixel
        const int bb = pg / HW;
        const int rr2 = pg - bb * HW;
        float* ob = out + (size_t)bb * 64 * HW + rr2;

        #pragma unroll
        for (int jj = 0; jj < 2; jj++) {
            const int g = 2 * gq + jj;
            uint4 pk = s_buf[px * 10 + g];
            float2 f0 = __half22float2(*(__half2*)&pk.x);
            float2 f1 = __half22float2(*(__half2*)&pk.y);
            float2 f2 = __half22float2(*(__half2*)&pk.z);
            float2 f3 = __half22float2(*(__half2*)&pk.w);
            const int ch = 8 * g;
            ob[(ch + 0) * HW] = f0.x + s_bias[ch + 0];
            ob[(ch + 1) * HW] = f0.y + s_bias[ch + 1];
            ob[(ch + 2) * HW] = f1.x + s_bias[ch + 2];
            ob[(ch + 3) * HW] = f1.y + s_bias[ch + 3];
            ob[(ch + 4) * HW] = f2.x + s_bias[ch + 4];
            ob[(ch + 5) * HW] = f2.y + s_bias[ch + 5];
            ob[(ch + 6) * HW] = f3.x + s_bias[ch + 6];
            ob[(ch + 7) * HW] = f3.y + s_bias[ch + 7];
        }
    }
}

extern "C" void kernel_launch(void* const* d_in, const int* in_sizes, int n_in,
                              void* d_out, int out_size)
{
    const float* x    = (const float*)d_in[0];
    const int*   sidx = (const int*)  d_in[1];
    const float* sval = (const float*)d_in[2];
    const float* lut  = (const float*)d_in[3];
    const float* bias = (const float*)d_in[4];
    float* out = (float*)d_out;

    maddness_conv2d_kernel<<<NBLK, TPB>>>(x, sidx, sval, lut, bias, out);
}